// round 14
// baseline (speedup 1.0000x reference)
#include <cuda_runtime.h>

#define N_NODES 50000
#define N_EDGES 800000
#define QUADS   (N_EDGES / 4)
#define F 128
#define BM_WORDS ((N_NODES + 31) / 32)

// ---- scratch (static device arrays; zero-initialized; no allocation allowed) ----
__device__ unsigned g_bm1[BM_WORDS];
__device__ unsigned g_bm2[BM_WORDS];
__device__ int   g_list1[N_NODES];
__device__ int   g_list2[512];
__device__ int   g_deg1[N_NODES];
__device__ int   g_deg2[N_NODES];
__device__ int2  g_elist2[N_EDGES];
__device__ int   g_n1, g_n2, g_ne2;
__device__ float g_agg1[N_NODES * F];   // invariant: zero at call entry (gemm re-zeroes)
__device__ float g_agg2[N_NODES * F];   // invariant: zero at call entry (gemm re-zeroes)
__device__ float g_h1[N_NODES * F];
__device__ float g_h2[N_NODES * F];

__device__ __forceinline__ bool bm_test(const unsigned* bm, int n) {
    return (bm[n >> 5] >> (n & 31)) & 1u;
}

// ---------------- init: zero bitmaps+counters, insert S2 seeds (1 block) -------
__global__ void __launch_bounds__(512) init_kernel(const int* __restrict__ states,
                                                   int n_states,
                                                   const int* __restrict__ actions) {
    int tid = threadIdx.x;
    for (int i = tid; i < BM_WORDS; i += 512) { g_bm1[i] = 0u; g_bm2[i] = 0u; }
    if (tid == 0) { g_n1 = 0; g_n2 = 0; g_ne2 = 0; }
    __syncthreads();
    for (int t = tid; t <= n_states; t += 512) {
        int node = (t < n_states) ? states[t] : actions[0];
        unsigned bit = 1u << (node & 31);
        unsigned old2 = atomicOr(&g_bm2[node >> 5], bit);
        if (!(old2 & bit)) {
            int p = atomicAdd(&g_n2, 1);
            g_list2[p] = node;
            g_deg2[node] = 0;
        }
        unsigned old1 = atomicOr(&g_bm1[node >> 5], bit);
        if (!(old1 & bit)) {
            int p = atomicAdd(&g_n1, 1);
            g_list1[p] = node;
            g_deg1[node] = 0;
        }
    }
}

// ---------------- pass A: edges into S2 -> elist2 (+deg2), sources -> S1 -------
__global__ void __launch_bounds__(256) passA_kernel(const int* __restrict__ src,
                                                    const int* __restrict__ dst) {
    __shared__ int s_cnt, s_base;
    if (threadIdx.x == 0) s_cnt = 0;
    __syncthreads();

    int i4 = blockIdx.x * blockDim.x + threadIdx.x;
    int lane = threadIdx.x & 31;
    bool valid = (i4 * 4 < N_EDGES);
    int4 d4 = valid ? ((const int4*)dst)[i4] : make_int4(0, 0, 0, 0);
    int4 s4 = valid ? ((const int4*)src)[i4] : make_int4(0, 0, 0, 0);
    int dv[4] = {d4.x, d4.y, d4.z, d4.w};
    int sv[4] = {s4.x, s4.y, s4.z, s4.w};
    bool pass[4];
    int my = 0;
#pragma unroll
    for (int j = 0; j < 4; j++) {
        pass[j] = valid && bm_test(g_bm2, dv[j]);
        my += pass[j] ? 1 : 0;
    }
    int scan = my;
#pragma unroll
    for (int d = 1; d < 32; d <<= 1) {
        int t = __shfl_up_sync(0xffffffff, scan, d);
        if (lane >= d) scan += t;
    }
    int wtotal = __shfl_sync(0xffffffff, scan, 31);
    int wbase = 0;
    if (lane == 31 && wtotal > 0) wbase = atomicAdd(&s_cnt, wtotal);
    wbase = __shfl_sync(0xffffffff, wbase, 31);
    int my_off = wbase + scan - my;
    __syncthreads();
    if (threadIdx.x == 0) s_base = (s_cnt > 0) ? atomicAdd(&g_ne2, s_cnt) : 0;
    __syncthreads();
    int p = s_base + my_off;
#pragma unroll
    for (int j = 0; j < 4; j++) {
        if (pass[j]) {
            g_elist2[p++] = make_int2(sv[j], dv[j]);
            atomicAdd(&g_deg2[dv[j]], 1);
            unsigned bit = 1u << (sv[j] & 31);
            unsigned old = atomicOr(&g_bm1[sv[j] >> 5], bit);
            if (!(old & bit)) {
                int q = atomicAdd(&g_n1, 1);
                g_list1[q] = sv[j];
                g_deg1[sv[j]] = 0;
            }
        }
    }
}

// ------- fused filter + layer-1 aggregation: ballot over bm1, warp red --------
__global__ void __launch_bounds__(256) filter_agg1_kernel(const int* __restrict__ src,
                                                          const int* __restrict__ dst,
                                                          const float* __restrict__ x) {
    int gw   = (blockIdx.x * blockDim.x + threadIdx.x) >> 5;
    int nw   = ((int)gridDim.x * blockDim.x) >> 5;
    int lane = threadIdx.x & 31;
    for (int base = gw * 32; base < N_EDGES; base += nw * 32) {
        int e = base + lane;
        int d = 0, s = 0;
        bool p = false;
        if (e < N_EDGES) {
            d = dst[e];
            p = bm_test(g_bm1, d);
        }
        unsigned mask = __ballot_sync(0xffffffff, p);
        if (p) s = src[e];
        while (mask) {
            int b = __ffs(mask) - 1;
            mask &= mask - 1;
            int ss = __shfl_sync(0xffffffff, s, b);
            int dd = __shfl_sync(0xffffffff, d, b);
            float4 v = ((const float4*)x)[ss * 32 + lane];
            float* a = &g_agg1[dd * F + lane * 4];
            asm volatile("red.global.add.v4.f32 [%0], {%1, %2, %3, %4};"
                         :: "l"(a), "f"(v.x), "f"(v.y), "f"(v.z), "f"(v.w) : "memory");
            if (lane == (unsigned)b) atomicAdd(&g_deg1[dd], 1);
        }
    }
}

// ---------------- edge aggregation for layer 2: warp per edge ------------------
__global__ void edge_agg_kernel(const int2* __restrict__ elist, const int* __restrict__ ne_p,
                                const float* __restrict__ feat, float* __restrict__ agg) {
    int ne = *ne_p;
    int nwarps = (gridDim.x * blockDim.x) >> 5;
    int warp = (blockIdx.x * blockDim.x + threadIdx.x) >> 5;
    int lane = threadIdx.x & 31;
    for (int j = warp; j < ne; j += nwarps) {
        int2 e = elist[j];
        float4 v = ((const float4*)feat)[e.x * 32 + lane];
        float* a = &agg[e.y * F + lane * 4];
        asm volatile("red.global.add.v4.f32 [%0], {%1, %2, %3, %4};"
                     :: "l"(a), "f"(v.x), "f"(v.y), "f"(v.z), "f"(v.w) : "memory");
    }
}

// ------- gathered fused SAGE GEMM: 16-row tiles, K-split 2 wg, reg prefetch ----
// out[node] = relu(feat[node]@Ws^T + (agg[node]/max(deg,1))@Wn^T + b)
// wg0: self half (feat,Ws).  wg1: neighbor half (agg,Wn; 1/deg fused).
// Each wg: 4 kt chunks, 128 threads, 2x8 accumulators, reg-prefetch double-buffer.
#define MT 16
#define KT 32

__global__ void __launch_bounds__(256) gemm_list_kernel(
    const int* __restrict__ list, const int* __restrict__ count_p,
    const float* __restrict__ feat, float* __restrict__ agg,
    const int* __restrict__ deg,
    const float* __restrict__ Ws, const float* __restrict__ Wn,
    const float* __restrict__ bias, float* __restrict__ out)
{
    int count = *count_p;
    int ntiles = (count + MT - 1) / MT;
    if (blockIdx.x >= ntiles) return;

    __shared__ int   rows[MT];
    __shared__ float invs[MT];
    __shared__ float As[2][KT][MT + 4];
    __shared__ float Bs[2][KT][128 + 4];

    int tid  = threadIdx.x;
    int wg   = tid >> 7;          // 0 or 1
    int wtid = tid & 127;
    int m0   = blockIdx.x * MT;
    int r0   = (wtid >> 4) * 2;   // 0..14 step 2
    int c0   = (wtid & 15) * 8;   // 0..120 step 8

    if (tid < MT) {
        int nd = (m0 + tid < count) ? list[m0 + tid] : -1;
        rows[tid] = nd;
        invs[tid] = (nd >= 0) ? 1.0f / (float)max(deg[nd], 1) : 0.f;
    }
    __syncthreads();

    const float* A = wg ? agg : feat;
    const float* W = wg ? Wn : Ws;

    // per-thread fragments: A 1 float4 (16 rows x 8 q = 128), W 8 float4
    int a_row = wtid >> 3;
    int a_kq  = wtid & 7;

    float4 pa, pw[8];
    // prefetch kt=0
    {
        int nd = rows[a_row];
        pa = make_float4(0.f, 0.f, 0.f, 0.f);
        if (nd >= 0) pa = ((const float4*)A)[nd * 32 + a_kq];
    }
#pragma unroll
    for (int i = 0; i < 8; i++) {
        int v = wtid + 128 * i;
        pw[i] = ((const float4*)W)[(v >> 3) * 32 + (v & 7)];
    }

    float acc[2][8];
#pragma unroll
    for (int m = 0; m < 2; m++)
#pragma unroll
        for (int n = 0; n < 8; n++) acc[m][n] = 0.f;

#pragma unroll 1
    for (int kt = 0; kt < 4; kt++) {
        // store prefetched fragments to smem (scale agg half by 1/deg)
        {
            float sc = wg ? invs[a_row] : 1.0f;
            As[wg][a_kq * 4 + 0][a_row] = pa.x * sc;
            As[wg][a_kq * 4 + 1][a_row] = pa.y * sc;
            As[wg][a_kq * 4 + 2][a_row] = pa.z * sc;
            As[wg][a_kq * 4 + 3][a_row] = pa.w * sc;
        }
#pragma unroll
        for (int i = 0; i < 8; i++) {
            int v = wtid + 128 * i;
            Bs[wg][(v & 7) * 4 + 0][v >> 3] = pw[i].x;
            Bs[wg][(v & 7) * 4 + 1][v >> 3] = pw[i].y;
            Bs[wg][(v & 7) * 4 + 2][v >> 3] = pw[i].z;
            Bs[wg][(v & 7) * 4 + 3][v >> 3] = pw[i].w;
        }
        __syncthreads();

        // prefetch kt+1 while computing kt
        if (kt < 3) {
            int kb4 = (kt + 1) * 8;
            int nd = rows[a_row];
            pa = make_float4(0.f, 0.f, 0.f, 0.f);
            if (nd >= 0) pa = ((const float4*)A)[nd * 32 + kb4 + a_kq];
#pragma unroll
            for (int i = 0; i < 8; i++) {
                int v = wtid + 128 * i;
                pw[i] = ((const float4*)W)[(v >> 3) * 32 + kb4 + (v & 7)];
            }
        }

#pragma unroll
        for (int k = 0; k < KT; k++) {
            float2 a2 = *(const float2*)&As[wg][k][r0];
            float4 b0 = *(const float4*)&Bs[wg][k][c0];
            float4 b1 = *(const float4*)&Bs[wg][k][c0 + 4];
            float am[2] = {a2.x, a2.y};
            float bn[8] = {b0.x, b0.y, b0.z, b0.w, b1.x, b1.y, b1.z, b1.w};
#pragma unroll
            for (int m = 0; m < 2; m++)
#pragma unroll
                for (int n = 0; n < 8; n++)
                    acc[m][n] += am[m] * bn[n];
        }
        __syncthreads();
    }

    // combine: wg1 stores partials into smem (reuse Bs[1] as 16x132 buffer)
    float* part = &Bs[1][0][0];
    if (wg == 1) {
#pragma unroll
        for (int m = 0; m < 2; m++)
#pragma unroll
            for (int n = 0; n < 8; n++)
                part[(r0 + m) * 132 + c0 + n] = acc[m][n];
    }
    __syncthreads();

    if (wg == 0) {
        float bv[8];
#pragma unroll
        for (int n = 0; n < 8; n++) bv[n] = bias[c0 + n];
#pragma unroll
        for (int m = 0; m < 2; m++) {
            int nd = rows[r0 + m];
            if (nd >= 0) {
                float o[8];
#pragma unroll
                for (int n = 0; n < 8; n++)
                    o[n] = fmaxf(acc[m][n] + part[(r0 + m) * 132 + c0 + n] + bv[n], 0.f);
                float4 o0 = make_float4(o[0], o[1], o[2], o[3]);
                float4 o1 = make_float4(o[4], o[5], o[6], o[7]);
                ((float4*)out)[nd * 32 + (c0 >> 2)]     = o0;
                ((float4*)out)[nd * 32 + (c0 >> 2) + 1] = o1;
            }
        }
    } else {
        // wg1: re-zero consumed agg rows (16 rows x 32 float4 = 512, 4 per thread)
#pragma unroll
        for (int i = 0; i < 4; i++) {
            int v   = wtid + 128 * i;
            int row = v >> 5;
            int c   = v & 31;
            int nd  = rows[row];
            if (nd >= 0) ((float4*)agg)[nd * 32 + c] = make_float4(0.f, 0.f, 0.f, 0.f);
        }
    }
}

// ---------------- parallel readout (1 block, 1024 threads) ---------------------
__global__ void __launch_bounds__(1024) final_kernel(const int* __restrict__ states,
                                                     int n_states,
                                                     const int* __restrict__ actions,
                                                     const float* __restrict__ Wfc,
                                                     const float* __restrict__ bfc,
                                                     float* __restrict__ out)
{
    __shared__ int   smax[F];
    __shared__ float red[F];
    int tid  = threadIdx.x;
    int wid  = tid >> 5;
    int lane = tid & 31;

    if (tid < F) smax[tid] = 0;        // 0.0f bits; h2 is post-ReLU (>= 0)
    __syncthreads();

    float4 m = make_float4(0.f, 0.f, 0.f, 0.f);
    for (int s = wid; s < n_states; s += 32) {
        float4 v = ((const float4*)g_h2)[states[s] * 32 + lane];
        m.x = fmaxf(m.x, v.x); m.y = fmaxf(m.y, v.y);
        m.z = fmaxf(m.z, v.z); m.w = fmaxf(m.w, v.w);
    }
    atomicMax(&smax[lane * 4 + 0], __float_as_int(m.x));
    atomicMax(&smax[lane * 4 + 1], __float_as_int(m.y));
    atomicMax(&smax[lane * 4 + 2], __float_as_int(m.z));
    atomicMax(&smax[lane * 4 + 3], __float_as_int(m.w));
    __syncthreads();

    if (tid < F) {
        float mm = __int_as_float(smax[tid]);
        float av = g_h2[actions[0] * F + tid];
        red[tid] = mm * Wfc[tid] + av * Wfc[F + tid];
    }
    __syncthreads();
    for (int d = 64; d > 0; d >>= 1) {
        if (tid < d) red[tid] += red[tid + d];
        __syncthreads();
    }
    if (tid == 0) out[0] = red[0] + bfc[0];
}

// ---------------- launch ----------------
extern "C" void kernel_launch(void* const* d_in, const int* in_sizes, int n_in,
                              void* d_out, int out_size) {
    const float* x      = (const float*)d_in[0];
    const int*   esrc   = (const int*)d_in[1];
    const int*   edst   = (const int*)d_in[2];
    const int*   states = (const int*)d_in[3];
    const int*   actions= (const int*)d_in[4];
    const float* W1s    = (const float*)d_in[5];
    const float* W1n    = (const float*)d_in[6];
    const float* b1     = (const float*)d_in[7];
    const float* W2s    = (const float*)d_in[8];
    const float* W2n    = (const float*)d_in[9];
    const float* b2     = (const float*)d_in[10];
    const float* Wfc    = (const float*)d_in[11];
    const float* bfc    = (const float*)d_in[12];
    float* out = (float*)d_out;
    int n_states = in_sizes[3];

    int *list1_p, *list2_p, *n1_p, *n2_p, *ne2_p, *deg1_p, *deg2_p;
    int2 *elist2_p;
    float *agg1_p, *agg2_p, *h1_p, *h2_p;
    cudaGetSymbolAddress((void**)&list1_p,  g_list1);
    cudaGetSymbolAddress((void**)&list2_p,  g_list2);
    cudaGetSymbolAddress((void**)&n1_p,     g_n1);
    cudaGetSymbolAddress((void**)&n2_p,     g_n2);
    cudaGetSymbolAddress((void**)&ne2_p,    g_ne2);
    cudaGetSymbolAddress((void**)&deg1_p,   g_deg1);
    cudaGetSymbolAddress((void**)&deg2_p,   g_deg2);
    cudaGetSymbolAddress((void**)&elist2_p, g_elist2);
    cudaGetSymbolAddress((void**)&agg1_p,   g_agg1);
    cudaGetSymbolAddress((void**)&agg2_p,   g_agg2);
    cudaGetSymbolAddress((void**)&h1_p,     g_h1);
    cudaGetSymbolAddress((void**)&h2_p,     g_h2);

    const int pass_blocks = (QUADS + 255) / 256;   // 782

    // frontier construction
    init_kernel<<<1, 512>>>(states, n_states, actions);
    passA_kernel<<<pass_blocks, 256>>>(esrc, edst);

    // layer 1: fused filter + aggregation, then GEMM (re-zeroes agg1)
    filter_agg1_kernel<<<1024, 256>>>(esrc, edst, x);
    gemm_list_kernel<<<(N_NODES + MT - 1) / MT, 256>>>(list1_p, n1_p, x, agg1_p, deg1_p,
                                                       W1s, W1n, b1, h1_p);

    // layer 2: aggregation over elist2, then GEMM (re-zeroes agg2)
    edge_agg_kernel<<<512, 256>>>(elist2_p, ne2_p, h1_p, agg2_p);
    gemm_list_kernel<<<17, 256>>>(list2_p, n2_p, h1_p, agg2_p, deg2_p,
                                  W2s, W2n, b2, h2_p);

    // readout
    final_kernel<<<1, 1024>>>(states, n_states, actions, Wfc, bfc, out);
}

// round 17
// speedup vs baseline: 1.2873x; 1.2873x over previous
#include <cuda_runtime.h>

#define N_NODES 50000
#define N_EDGES 800000
#define QUADS   (N_EDGES / 4)
#define F 128
#define BM_WORDS ((N_NODES + 31) / 32)

// ---- scratch (static device arrays; zero-initialized; no allocation allowed) ----
__device__ unsigned g_bm1[BM_WORDS];
__device__ unsigned g_bm2[BM_WORDS];
__device__ int   g_list1[N_NODES];
__device__ int   g_list2[512];
__device__ int   g_deg1[N_NODES];
__device__ int   g_deg2[N_NODES];
__device__ int2  g_elist2[N_EDGES];
__device__ int   g_n1, g_n2, g_ne2;
__device__ float g_agg1[N_NODES * F];   // invariant: zero at call entry (edge_agg re-zeroes)
__device__ float g_agg2[N_NODES * F];   // invariant: zero at call entry (final re-zeroes)
__device__ float g_h1[N_NODES * F];
__device__ float g_h2[N_NODES * F];

__device__ __forceinline__ bool bm_test(const unsigned* bm, int n) {
    return (bm[n >> 5] >> (n & 31)) & 1u;
}

// ---------------- init: zero bitmaps+counters, insert S2 seeds (1 block) -------
__global__ void __launch_bounds__(512) init_kernel(const int* __restrict__ states,
                                                   int n_states,
                                                   const int* __restrict__ actions) {
    int tid = threadIdx.x;
    for (int i = tid; i < BM_WORDS; i += 512) { g_bm1[i] = 0u; g_bm2[i] = 0u; }
    if (tid == 0) { g_n1 = 0; g_n2 = 0; g_ne2 = 0; }
    __syncthreads();
    for (int t = tid; t <= n_states; t += 512) {
        int node = (t < n_states) ? states[t] : actions[0];
        unsigned bit = 1u << (node & 31);
        unsigned old2 = atomicOr(&g_bm2[node >> 5], bit);
        if (!(old2 & bit)) {
            int p = atomicAdd(&g_n2, 1);
            g_list2[p] = node;
            g_deg2[node] = 0;
        }
        unsigned old1 = atomicOr(&g_bm1[node >> 5], bit);
        if (!(old1 & bit)) {
            int p = atomicAdd(&g_n1, 1);
            g_list1[p] = node;
            g_deg1[node] = 0;
        }
    }
}

// ---------------- pass A: edges into S2 -> elist2 (+deg2), sources -> S1 -------
__global__ void __launch_bounds__(256) passA_kernel(const int* __restrict__ src,
                                                    const int* __restrict__ dst) {
    __shared__ int s_cnt, s_base;
    if (threadIdx.x == 0) s_cnt = 0;
    __syncthreads();

    int i4 = blockIdx.x * blockDim.x + threadIdx.x;
    int lane = threadIdx.x & 31;
    bool valid = (i4 * 4 < N_EDGES);
    int4 d4 = valid ? ((const int4*)dst)[i4] : make_int4(0, 0, 0, 0);
    int4 s4 = valid ? ((const int4*)src)[i4] : make_int4(0, 0, 0, 0);
    int dv[4] = {d4.x, d4.y, d4.z, d4.w};
    int sv[4] = {s4.x, s4.y, s4.z, s4.w};
    bool pass[4];
    int my = 0;
#pragma unroll
    for (int j = 0; j < 4; j++) {
        pass[j] = valid && bm_test(g_bm2, dv[j]);
        my += pass[j] ? 1 : 0;
    }
    int scan = my;
#pragma unroll
    for (int d = 1; d < 32; d <<= 1) {
        int t = __shfl_up_sync(0xffffffff, scan, d);
        if (lane >= d) scan += t;
    }
    int wtotal = __shfl_sync(0xffffffff, scan, 31);
    int wbase = 0;
    if (lane == 31 && wtotal > 0) wbase = atomicAdd(&s_cnt, wtotal);
    wbase = __shfl_sync(0xffffffff, wbase, 31);
    int my_off = wbase + scan - my;
    __syncthreads();
    if (threadIdx.x == 0) s_base = (s_cnt > 0) ? atomicAdd(&g_ne2, s_cnt) : 0;
    __syncthreads();
    int p = s_base + my_off;
#pragma unroll
    for (int j = 0; j < 4; j++) {
        if (pass[j]) {
            g_elist2[p++] = make_int2(sv[j], dv[j]);
            atomicAdd(&g_deg2[dv[j]], 1);
            unsigned bit = 1u << (sv[j] & 31);
            unsigned old = atomicOr(&g_bm1[sv[j] >> 5], bit);
            if (!(old & bit)) {
                int q = atomicAdd(&g_n1, 1);
                g_list1[q] = sv[j];
                g_deg1[sv[j]] = 0;
            }
        }
    }
}

// ------- fused filter + layer-1 aggregation: ballot over bm1, warp red --------
__global__ void __launch_bounds__(256) filter_agg1_kernel(const int* __restrict__ src,
                                                          const int* __restrict__ dst,
                                                          const float* __restrict__ x) {
    int gw   = (blockIdx.x * blockDim.x + threadIdx.x) >> 5;
    int nw   = ((int)gridDim.x * blockDim.x) >> 5;
    int lane = threadIdx.x & 31;
    for (int base = gw * 32; base < N_EDGES; base += nw * 32) {
        int e = base + lane;
        int d = 0, s = 0;
        bool p = false;
        if (e < N_EDGES) {
            d = dst[e];
            p = bm_test(g_bm1, d);
        }
        unsigned mask = __ballot_sync(0xffffffff, p);
        if (p) s = src[e];
        while (mask) {
            int b = __ffs(mask) - 1;
            mask &= mask - 1;
            int ss = __shfl_sync(0xffffffff, s, b);
            int dd = __shfl_sync(0xffffffff, d, b);
            float4 v = ((const float4*)x)[ss * 32 + lane];
            float* a = &g_agg1[dd * F + lane * 4];
            asm volatile("red.global.add.v4.f32 [%0], {%1, %2, %3, %4};"
                         :: "l"(a), "f"(v.x), "f"(v.y), "f"(v.z), "f"(v.w) : "memory");
            if (lane == (unsigned)b) atomicAdd(&g_deg1[dd], 1);
        }
    }
}

// ------- layer-2 aggregation (+ re-zero of agg1 rows consumed by gemm1) --------
__global__ void edge_agg_kernel(const int2* __restrict__ elist, const int* __restrict__ ne_p,
                                const float* __restrict__ feat, float* __restrict__ agg) {
    // re-zero agg1 rows for list1 (gemm1 finished before this launch)
    {
        int n1 = g_n1;
        int gw   = (blockIdx.x * blockDim.x + threadIdx.x) >> 5;
        int nw   = ((int)gridDim.x * blockDim.x) >> 5;
        int lane = threadIdx.x & 31;
        for (int w = gw; w < n1; w += nw)
            ((float4*)g_agg1)[g_list1[w] * 32 + lane] = make_float4(0.f, 0.f, 0.f, 0.f);
    }

    int ne = *ne_p;
    int nwarps = (gridDim.x * blockDim.x) >> 5;
    int warp = (blockIdx.x * blockDim.x + threadIdx.x) >> 5;
    int lane = threadIdx.x & 31;
    for (int j = warp; j < ne; j += nwarps) {
        int2 e = elist[j];
        float4 v = ((const float4*)feat)[e.x * 32 + lane];
        float* a = &agg[e.y * F + lane * 4];
        asm volatile("red.global.add.v4.f32 [%0], {%1, %2, %3, %4};"
                     :: "l"(a), "f"(v.x), "f"(v.y), "f"(v.z), "f"(v.w) : "memory");
    }
}

// ------- gathered fused SAGE GEMM: 32-row tiles, N-split x2, K-split 2 wg ------
// Each block: 32 rows x 64 cols (chalf selects col half). wg0 = self (feat,Ws),
// wg1 = neighbor (agg,Wn; 1/deg fused). 4 kt chunks, reg-prefetch double-buffer,
// acc[4][4] per thread. No agg re-zero here (done downstream).
#define MT 32
#define KT 32

__global__ void __launch_bounds__(256) gemm_list_kernel(
    const int* __restrict__ list, const int* __restrict__ count_p,
    const float* __restrict__ feat, const float* __restrict__ agg,
    const int* __restrict__ deg,
    const float* __restrict__ Ws, const float* __restrict__ Wn,
    const float* __restrict__ bias, float* __restrict__ out)
{
    int count = *count_p;
    int ntiles = (count + MT - 1) / MT;
    int tile  = blockIdx.x >> 1;
    int chalf = blockIdx.x & 1;
    if (tile >= ntiles) return;

    __shared__ int   rows[MT];
    __shared__ float invs[MT];
    __shared__ float As[2][KT][MT + 4];
    __shared__ float Bs[2][KT][64 + 4];

    int tid  = threadIdx.x;
    int wg   = tid >> 7;          // 0 or 1
    int wtid = tid & 127;
    int m0   = tile * MT;
    int r0   = (wtid >> 4) * 4;   // 0..28 step 4
    int c0   = (wtid & 15) * 4;   // 0..60 step 4 (within 64-col half)
    int cbase = chalf * 64;

    if (tid < MT) {
        int nd = (m0 + tid < count) ? list[m0 + tid] : -1;
        rows[tid] = nd;
        invs[tid] = (nd >= 0) ? 1.0f / (float)max(deg[nd], 1) : 0.f;
    }
    __syncthreads();

    const float* A = wg ? agg : feat;
    const float* W = wg ? Wn : Ws;

    // per-thread fragments: A 2 float4 (32 rows x 8 q), W 4 float4 (64 cols x 8 q)
    int a_row[2], a_kq[2];
#pragma unroll
    for (int i = 0; i < 2; i++) { int v = wtid + 128 * i; a_row[i] = v >> 3; a_kq[i] = v & 7; }

    float4 pa[2], pw[4];
    // prefetch kt=0
#pragma unroll
    for (int i = 0; i < 2; i++) {
        int nd = rows[a_row[i]];
        pa[i] = make_float4(0.f, 0.f, 0.f, 0.f);
        if (nd >= 0) pa[i] = ((const float4*)A)[nd * 32 + a_kq[i]];
    }
#pragma unroll
    for (int i = 0; i < 4; i++) {
        int v = wtid + 128 * i;
        pw[i] = ((const float4*)W)[(cbase + (v >> 3)) * 32 + (v & 7)];
    }

    float acc[4][4];
#pragma unroll
    for (int m = 0; m < 4; m++)
#pragma unroll
        for (int n = 0; n < 4; n++) acc[m][n] = 0.f;

#pragma unroll 1
    for (int kt = 0; kt < 4; kt++) {
        // store prefetched fragments to smem (scale agg half by 1/deg)
#pragma unroll
        for (int i = 0; i < 2; i++) {
            float sc = wg ? invs[a_row[i]] : 1.0f;
            As[wg][a_kq[i] * 4 + 0][a_row[i]] = pa[i].x * sc;
            As[wg][a_kq[i] * 4 + 1][a_row[i]] = pa[i].y * sc;
            As[wg][a_kq[i] * 4 + 2][a_row[i]] = pa[i].z * sc;
            As[wg][a_kq[i] * 4 + 3][a_row[i]] = pa[i].w * sc;
        }
#pragma unroll
        for (int i = 0; i < 4; i++) {
            int v = wtid + 128 * i;
            Bs[wg][(v & 7) * 4 + 0][v >> 3] = pw[i].x;
            Bs[wg][(v & 7) * 4 + 1][v >> 3] = pw[i].y;
            Bs[wg][(v & 7) * 4 + 2][v >> 3] = pw[i].z;
            Bs[wg][(v & 7) * 4 + 3][v >> 3] = pw[i].w;
        }
        __syncthreads();

        // prefetch kt+1 while computing kt
        if (kt < 3) {
            int kb4 = (kt + 1) * 8;
#pragma unroll
            for (int i = 0; i < 2; i++) {
                int nd = rows[a_row[i]];
                pa[i] = make_float4(0.f, 0.f, 0.f, 0.f);
                if (nd >= 0) pa[i] = ((const float4*)A)[nd * 32 + kb4 + a_kq[i]];
            }
#pragma unroll
            for (int i = 0; i < 4; i++) {
                int v = wtid + 128 * i;
                pw[i] = ((const float4*)W)[(cbase + (v >> 3)) * 32 + kb4 + (v & 7)];
            }
        }

#pragma unroll
        for (int k = 0; k < KT; k++) {
            float4 a4 = *(const float4*)&As[wg][k][r0];
            float4 b0 = *(const float4*)&Bs[wg][k][c0];
            float am[4] = {a4.x, a4.y, a4.z, a4.w};
            float bn[4] = {b0.x, b0.y, b0.z, b0.w};
#pragma unroll
            for (int m = 0; m < 4; m++)
#pragma unroll
                for (int n = 0; n < 4; n++)
                    acc[m][n] += am[m] * bn[n];
        }
        __syncthreads();
    }

    // combine: wg1 stores partials into smem (reuse Bs[1] as 32x68 buffer)
    float* part = &Bs[1][0][0];
    if (wg == 1) {
#pragma unroll
        for (int m = 0; m < 4; m++)
#pragma unroll
            for (int n = 0; n < 4; n++)
                part[(r0 + m) * 68 + c0 + n] = acc[m][n];
    }
    __syncthreads();

    if (wg == 0) {
        float bv[4];
#pragma unroll
        for (int n = 0; n < 4; n++) bv[n] = bias[cbase + c0 + n];
#pragma unroll
        for (int m = 0; m < 4; m++) {
            int nd = rows[r0 + m];
            if (nd >= 0) {
                float o[4];
#pragma unroll
                for (int n = 0; n < 4; n++)
                    o[n] = fmaxf(acc[m][n] + part[(r0 + m) * 68 + c0 + n] + bv[n], 0.f);
                ((float4*)out)[nd * 32 + ((cbase + c0) >> 2)] =
                    make_float4(o[0], o[1], o[2], o[3]);
            }
        }
    }
}

// ------- parallel readout (1 block, 1024 threads) + agg2 re-zero ---------------
__global__ void __launch_bounds__(1024) final_kernel(const int* __restrict__ states,
                                                     int n_states,
                                                     const int* __restrict__ actions,
                                                     const float* __restrict__ Wfc,
                                                     const float* __restrict__ bfc,
                                                     float* __restrict__ out)
{
    __shared__ int   smax[F];
    __shared__ float red[F];
    int tid  = threadIdx.x;
    int wid  = tid >> 5;
    int lane = tid & 31;

    // re-zero agg2 rows for list2 (gemm2 finished before this launch)
    {
        int n2 = g_n2;
        for (int w = wid; w < n2; w += 32)
            ((float4*)g_agg2)[g_list2[w] * 32 + lane] = make_float4(0.f, 0.f, 0.f, 0.f);
    }

    if (tid < F) smax[tid] = 0;        // 0.0f bits; h2 is post-ReLU (>= 0)
    __syncthreads();

    float4 m = make_float4(0.f, 0.f, 0.f, 0.f);
    for (int s = wid; s < n_states; s += 32) {
        float4 v = ((const float4*)g_h2)[states[s] * 32 + lane];
        m.x = fmaxf(m.x, v.x); m.y = fmaxf(m.y, v.y);
        m.z = fmaxf(m.z, v.z); m.w = fmaxf(m.w, v.w);
    }
    atomicMax(&smax[lane * 4 + 0], __float_as_int(m.x));
    atomicMax(&smax[lane * 4 + 1], __float_as_int(m.y));
    atomicMax(&smax[lane * 4 + 2], __float_as_int(m.z));
    atomicMax(&smax[lane * 4 + 3], __float_as_int(m.w));
    __syncthreads();

    if (tid < F) {
        float mm = __int_as_float(smax[tid]);
        float av = g_h2[actions[0] * F + tid];
        red[tid] = mm * Wfc[tid] + av * Wfc[F + tid];
    }
    __syncthreads();
    for (int d = 64; d > 0; d >>= 1) {
        if (tid < d) red[tid] += red[tid + d];
        __syncthreads();
    }
    if (tid == 0) out[0] = red[0] + bfc[0];
}

// ---------------- launch ----------------
extern "C" void kernel_launch(void* const* d_in, const int* in_sizes, int n_in,
                              void* d_out, int out_size) {
    const float* x      = (const float*)d_in[0];
    const int*   esrc   = (const int*)d_in[1];
    const int*   edst   = (const int*)d_in[2];
    const int*   states = (const int*)d_in[3];
    const int*   actions= (const int*)d_in[4];
    const float* W1s    = (const float*)d_in[5];
    const float* W1n    = (const float*)d_in[6];
    const float* b1     = (const float*)d_in[7];
    const float* W2s    = (const float*)d_in[8];
    const float* W2n    = (const float*)d_in[9];
    const float* b2     = (const float*)d_in[10];
    const float* Wfc    = (const float*)d_in[11];
    const float* bfc    = (const float*)d_in[12];
    float* out = (float*)d_out;
    int n_states = in_sizes[3];

    int *list1_p, *list2_p, *n1_p, *n2_p, *ne2_p, *deg1_p, *deg2_p;
    int2 *elist2_p;
    float *agg1_p, *agg2_p, *h1_p, *h2_p;
    cudaGetSymbolAddress((void**)&list1_p,  g_list1);
    cudaGetSymbolAddress((void**)&list2_p,  g_list2);
    cudaGetSymbolAddress((void**)&n1_p,     g_n1);
    cudaGetSymbolAddress((void**)&n2_p,     g_n2);
    cudaGetSymbolAddress((void**)&ne2_p,    g_ne2);
    cudaGetSymbolAddress((void**)&deg1_p,   g_deg1);
    cudaGetSymbolAddress((void**)&deg2_p,   g_deg2);
    cudaGetSymbolAddress((void**)&elist2_p, g_elist2);
    cudaGetSymbolAddress((void**)&agg1_p,   g_agg1);
    cudaGetSymbolAddress((void**)&agg2_p,   g_agg2);
    cudaGetSymbolAddress((void**)&h1_p,     g_h1);
    cudaGetSymbolAddress((void**)&h2_p,     g_h2);

    const int pass_blocks = (QUADS + 255) / 256;   // 782

    // frontier construction
    init_kernel<<<1, 512>>>(states, n_states, actions);
    passA_kernel<<<pass_blocks, 256>>>(esrc, edst);

    // layer 1: fused filter + aggregation, then GEMM (N-split x2)
    filter_agg1_kernel<<<1024, 256>>>(esrc, edst, x);
    gemm_list_kernel<<<((N_NODES + MT - 1) / MT) * 2, 256>>>(list1_p, n1_p, x, agg1_p,
                                                             deg1_p, W1s, W1n, b1, h1_p);

    // layer 2: aggregation (+agg1 re-zero), then GEMM
    edge_agg_kernel<<<512, 256>>>(elist2_p, ne2_p, h1_p, agg2_p);
    gemm_list_kernel<<<32, 256>>>(list2_p, n2_p, h1_p, agg2_p, deg2_p,
                                  W2s, W2n, b2, h2_p);

    // readout (+agg2 re-zero)
    final_kernel<<<1, 1024>>>(states, n_states, actions, Wfc, bfc, out);
}